// round 14
// baseline (speedup 1.0000x reference)
#include <cuda_runtime.h>
#include <cuda_bf16.h>
#include <cstdint>

#define IN_F     4096
#define OUT_F    11008
#define MROWS    32
#define GRP      128
#define KSPLIT   4
#define KPER     (IN_F / KSPLIT)          // 1024
#define STAGE_K  32
#define NSTAGES  (KPER / STAGE_K)         // 32
#define NBUF     4
#define NTILE    64
#define CTAS_COL (OUT_F / NTILE)          // 172
#define THREADS  128

#define XROW_B   272                      // x row: 256B bf16 + 16B pad (ldmatrix conflict-free)
#define WROW_B   272                      // W row: 64 int32 (256B) + 16B pad -> conflict-free LDS
#define WSTAGE_B (STAGE_K * WROW_B)       // 8704 per stage

// K-split partial sums + per-tile arrival counters (device globals: allowed)
__device__ float    g_partial[(size_t)KSPLIT * MROWS * OUT_F];   // 5.6 MB
__device__ unsigned g_cnt[CTAS_COL];                             // zero-init; self-resets

__device__ __forceinline__ float bfr(float v) {
    return __bfloat162float(__float2bfloat16(v));
}

__device__ __forceinline__ uint32_t pack_bf16x2(float hi, float lo) {
    uint32_t r;
    asm("cvt.rn.bf16x2.f32 %0, %1, %2;" : "=r"(r) : "f"(hi), "f"(lo));
    return r;
}

__device__ __forceinline__ void hmma(float c[4], const uint32_t a[4],
                                     uint32_t b0, uint32_t b1) {
    asm volatile(
        "mma.sync.aligned.m16n8k16.row.col.f32.bf16.bf16.f32 "
        "{%0,%1,%2,%3}, {%4,%5,%6,%7}, {%8,%9}, {%0,%1,%2,%3};"
        : "+f"(c[0]), "+f"(c[1]), "+f"(c[2]), "+f"(c[3])
        : "r"(a[0]), "r"(a[1]), "r"(a[2]), "r"(a[3]), "r"(b0), "r"(b1));
}

// ---------------------------------------------------------------------------
// Single kernel: R13's streaming GEMM + fused K-split reduction.
// Per CTA: 64 output cols x 1024 K, cp.async 4-buffer ring (3 in flight),
// B converts on-read ((qw-qz) 5-bit, bf16-exact), per-group scale epilogue.
// K-split partials go to scratch via STG; the LAST arriving CTA per column
// tile sums 4 partials + bf16(bias) and writes out (threadFenceReduction).
// ---------------------------------------------------------------------------
__global__ void __launch_bounds__(THREADS, 5)
qmain(const float* __restrict__ x, const int* __restrict__ qweight,
      const int* __restrict__ qzeros, const float* __restrict__ scales,
      const float* __restrict__ bias, float* __restrict__ out)
{
    __shared__ __align__(16) uint8_t xs_raw[MROWS * XROW_B];     //  8704 B
    __shared__ __align__(16) uint8_t ws_raw[NBUF * WSTAGE_B];    // 34816 B
    __shared__ unsigned s_last;

    uint32_t xs_b, ws_b;
    asm("{ .reg .u64 t; cvta.to.shared.u64 t, %1; cvt.u32.u64 %0, t; }"
        : "=r"(xs_b) : "l"(xs_raw));
    asm("{ .reg .u64 t; cvta.to.shared.u64 t, %1; cvt.u32.u64 %0, t; }"
        : "=r"(ws_b) : "l"(ws_raw));

    const int tid   = threadIdx.x;
    const int w     = tid >> 5;
    const int l     = tid & 31;
    const int bx    = blockIdx.x;
    const int ctile = bx % CTAS_COL;
    const int kq    = bx / CTAS_COL;
    const int o0    = ctile * NTILE;
    const int k0    = kq * KPER;

    const int gid = l >> 2;
    const int tig = l & 3;
    const int nc0 = o0 + w * 16 + gid;      // B column, t=0
    const int nc1 = nc0 + 8;                // B column, t=1
    const int cc  = o0 + w * 16 + 2 * tig;  // C column base

    const uint32_t a_lane_off = (uint32_t)(l & 15) * XROW_B + (uint32_t)(l >> 4) * 16;
    const uint32_t b_off0 = (uint32_t)(2 * tig) * WROW_B + (uint32_t)(w * 16 + gid) * 4;
    const uint32_t b_off1 = b_off0 + 32;    // +8 cols

    // cp.async mapping: row = tid>>4 (+8j), seg = tid&15 (16B); 4 ops/thread
    const int cp_row0 = tid >> 4;
    const int cp_seg  = tid & 15;

    float ct[2][2][4], cg[2][2][4];
    #pragma unroll
    for (int mi = 0; mi < 2; mi++)
        #pragma unroll
        for (int t = 0; t < 2; t++)
            #pragma unroll
            for (int r = 0; r < 4; r++) { ct[mi][t][r] = 0.0f; cg[mi][t][r] = 0.0f; }

    int qz0 = 0, qz1 = 0;

    auto issue_cp = [&](int s) {
        const uint32_t dst0 = ws_b + (uint32_t)(s & (NBUF - 1)) * WSTAGE_B;
        const int* src0 = qweight + (size_t)(k0 + s * STAGE_K) * OUT_F + o0;
        #pragma unroll
        for (int j = 0; j < 4; j++) {
            int row = cp_row0 + 8 * j;
            uint32_t dst = dst0 + (uint32_t)row * WROW_B + (uint32_t)cp_seg * 16;
            const int* src = src0 + (size_t)row * OUT_F + cp_seg * 4;
            asm volatile("cp.async.cg.shared.global [%0], [%1], 16;" :: "r"(dst), "l"(src));
        }
        asm volatile("cp.async.commit_group;" ::: "memory");
    };

    // ---- prologue: 3 stages in flight ----
    issue_cp(0);
    issue_cp(1);
    issue_cp(2);

    for (int st = 0; st < NSTAGES; st++) {
        const int g  = st >> 2;                 // 4 stages per 128k group
        const int gg = (k0 >> 7) + g;
        const int kb = k0 + g * GRP;

        if (st <= NSTAGES - 3)      asm volatile("cp.async.wait_group 2;" ::: "memory");
        else if (st == NSTAGES - 2) asm volatile("cp.async.wait_group 1;" ::: "memory");
        else                        asm volatile("cp.async.wait_group 0;" ::: "memory");
        __syncthreads();   // copies visible; prior stage reads done (WAR)

        if (st + 3 < NSTAGES) issue_cp(st + 3);

        if ((st & 3) == 0) {
            #pragma unroll
            for (int j = 0; j < 8; j++) {
                int idx = tid + THREADS * j;      // 0..1023
                int s   = idx >> 5;               // row 0..31
                int kq4 = idx & 31;
                float4 v = *(const float4*)(x + (size_t)s * IN_F + kb + 4 * kq4);
                uint32_t p0 = pack_bf16x2(v.y, v.x);
                uint32_t p1 = pack_bf16x2(v.w, v.z);
                uint32_t a = xs_b + (uint32_t)s * XROW_B + (uint32_t)kq4 * 8;
                asm volatile("st.shared.v2.b32 [%0], {%1,%2};" :: "r"(a), "r"(p0), "r"(p1));
            }
            qz0 = qzeros[(size_t)gg * OUT_F + nc0];
            qz1 = qzeros[(size_t)gg * OUT_F + nc1];
            __syncthreads();   // xs visible
        }

        const uint32_t rbuf = ws_b + (uint32_t)(st & (NBUF - 1)) * WSTAGE_B;

        #pragma unroll
        for (int ksl = 0; ksl < 2; ksl++) {
            const int ks = 2 * (st & 3) + ksl;

            uint32_t a0[4], a1[4];
            uint32_t addr0 = xs_b + a_lane_off + (uint32_t)ks * 32;
            uint32_t addr1 = addr0 + 16u * XROW_B;
            asm volatile("ldmatrix.sync.aligned.m8n8.x4.shared.b16 {%0,%1,%2,%3}, [%4];"
                         : "=r"(a0[0]), "=r"(a0[1]), "=r"(a0[2]), "=r"(a0[3]) : "r"(addr0));
            asm volatile("ldmatrix.sync.aligned.m8n8.x4.shared.b16 {%0,%1,%2,%3}, [%4];"
                         : "=r"(a1[0]), "=r"(a1[1]), "=r"(a1[2]), "=r"(a1[3]) : "r"(addr1));

            const uint32_t rb = rbuf + (uint32_t)(16 * ksl) * WROW_B;

            {   // t = 0
                int v0, v1, v2, v3;
                asm volatile("ld.shared.b32 %0, [%1];" : "=r"(v0) : "r"(rb + b_off0));
                asm volatile("ld.shared.b32 %0, [%1];" : "=r"(v1) : "r"(rb + b_off0 + WROW_B));
                asm volatile("ld.shared.b32 %0, [%1];" : "=r"(v2) : "r"(rb + b_off0 + 8 * WROW_B));
                asm volatile("ld.shared.b32 %0, [%1];" : "=r"(v3) : "r"(rb + b_off0 + 9 * WROW_B));
                uint32_t b0 = pack_bf16x2((float)(v1 - qz0), (float)(v0 - qz0));
                uint32_t b1 = pack_bf16x2((float)(v3 - qz0), (float)(v2 - qz0));
                hmma(cg[0][0], a0, b0, b1);
                hmma(cg[1][0], a1, b0, b1);
            }
            {   // t = 1
                int v0, v1, v2, v3;
                asm volatile("ld.shared.b32 %0, [%1];" : "=r"(v0) : "r"(rb + b_off1));
                asm volatile("ld.shared.b32 %0, [%1];" : "=r"(v1) : "r"(rb + b_off1 + WROW_B));
                asm volatile("ld.shared.b32 %0, [%1];" : "=r"(v2) : "r"(rb + b_off1 + 8 * WROW_B));
                asm volatile("ld.shared.b32 %0, [%1];" : "=r"(v3) : "r"(rb + b_off1 + 9 * WROW_B));
                uint32_t b0 = pack_bf16x2((float)(v1 - qz1), (float)(v0 - qz1));
                uint32_t b1 = pack_bf16x2((float)(v3 - qz1), (float)(v2 - qz1));
                hmma(cg[0][1], a0, b0, b1);
                hmma(cg[1][1], a1, b0, b1);
            }
        }

        if ((st & 3) == 3) {
            const float sA = bfr(scales[(size_t)gg * OUT_F + cc]);
            const float sB = bfr(scales[(size_t)gg * OUT_F + cc + 1]);
            const float sC = bfr(scales[(size_t)gg * OUT_F + cc + 8]);
            const float sD = bfr(scales[(size_t)gg * OUT_F + cc + 9]);
            #pragma unroll
            for (int mi = 0; mi < 2; mi++) {
                ct[mi][0][0] = fmaf(cg[mi][0][0], sA, ct[mi][0][0]);
                ct[mi][0][1] = fmaf(cg[mi][0][1], sB, ct[mi][0][1]);
                ct[mi][0][2] = fmaf(cg[mi][0][2], sA, ct[mi][0][2]);
                ct[mi][0][3] = fmaf(cg[mi][0][3], sB, ct[mi][0][3]);
                ct[mi][1][0] = fmaf(cg[mi][1][0], sC, ct[mi][1][0]);
                ct[mi][1][1] = fmaf(cg[mi][1][1], sD, ct[mi][1][1]);
                ct[mi][1][2] = fmaf(cg[mi][1][2], sC, ct[mi][1][2]);
                ct[mi][1][3] = fmaf(cg[mi][1][3], sD, ct[mi][1][3]);
                #pragma unroll
                for (int t = 0; t < 2; t++)
                    #pragma unroll
                    for (int r = 0; r < 4; r++) cg[mi][t][r] = 0.0f;
            }
        }
    }

    // ---- write K-split partial (plain STG, no atomics) ----
    float* pp = g_partial + (size_t)kq * MROWS * OUT_F;
    #pragma unroll
    for (int mi = 0; mi < 2; mi++) {
        int s0 = mi * 16 + gid;
        #pragma unroll
        for (int t = 0; t < 2; t++) {
            int oc = cc + t * 8;
            float2 lo = make_float2(ct[mi][t][0], ct[mi][t][1]);
            float2 hi = make_float2(ct[mi][t][2], ct[mi][t][3]);
            *(float2*)(pp + (size_t)s0 * OUT_F + oc)       = lo;
            *(float2*)(pp + (size_t)(s0 + 8) * OUT_F + oc) = hi;
        }
    }

    // ---- last CTA of this column tile reduces (threadFenceReduction) ----
    __syncthreads();
    __threadfence();
    if (tid == 0) {
        unsigned old = atomicInc(&g_cnt[ctile], KSPLIT - 1);  // wraps -> self-reset
        s_last = (old == KSPLIT - 1) ? 1u : 0u;
    }
    __syncthreads();

    if (s_last) {
        __threadfence();
        for (int i = tid; i < MROWS * NTILE; i += THREADS) {
            const int s = i >> 6;             // row 0..31
            const int oc = i & 63;            // local col
            const int o = o0 + oc;
            float a = bfr(bias[o]);
            #pragma unroll
            for (int p = 0; p < KSPLIT; p++)
                a += g_partial[((size_t)p * MROWS + s) * OUT_F + o];
            out[(size_t)s * OUT_F + o] = a;
        }
    }
}

// ---------------------------------------------------------------------------
// inputs: x f32[1,32,4096], qweight i32[4096,11008], qzeros i32[32,11008],
//         scales f32[32,11008], bias f32[11008]; output f32[1,32,11008]
// ---------------------------------------------------------------------------
extern "C" void kernel_launch(void* const* d_in, const int* in_sizes, int n_in,
                              void* d_out, int out_size)
{
    const float* x       = (const float*)d_in[0];
    const int*   qweight = (const int*)  d_in[1];
    const int*   qzeros  = (const int*)  d_in[2];
    const float* scales  = (const float*)d_in[3];
    const float* bias    = (const float*)d_in[4];
    float*       out     = (float*)d_out;

    qmain<<<CTAS_COL * KSPLIT, THREADS>>>(x, qweight, qzeros, scales, bias, out);
}

// round 15
// speedup vs baseline: 1.1009x; 1.1009x over previous
#include <cuda_runtime.h>
#include <cuda_bf16.h>
#include <cstdint>

#define IN_F     4096
#define OUT_F    11008
#define MROWS    32
#define GRP      128
#define KSPLIT   4
#define KPER     (IN_F / KSPLIT)          // 1024
#define STAGE_K  32
#define NSTAGES  (KPER / STAGE_K)         // 32
#define WNBUF    3
#define NTILE    64
#define CTAS_COL (OUT_F / NTILE)          // 172
#define THREADS  128

#define XROW_B   272                      // xs row: 256B bf16 + 16B pad (ldmatrix conflict-free)
#define XSTILE_B (MROWS * XROW_B)         // 8704 per group tile
#define WROW_B   272                      // W row: 64 int32 (256B) + 16B pad -> conflict-free LDS
#define WSTAGE_B (STAGE_K * WROW_B)       // 8704 per stage

// pre-converted bf16 x (written by init kernel), k-contiguous per row
__device__ __nv_bfloat16 g_xbf[(size_t)MROWS * IN_F];   // 256 KB

__device__ __forceinline__ float bfr(float v) {
    return __bfloat162float(__float2bfloat16(v));
}

__device__ __forceinline__ uint32_t pack_bf16x2(float hi, float lo) {
    uint32_t r;
    asm("cvt.rn.bf16x2.f32 %0, %1, %2;" : "=r"(r) : "f"(hi), "f"(lo));
    return r;
}

__device__ __forceinline__ void hmma(float c[4], const uint32_t a[4],
                                     uint32_t b0, uint32_t b1) {
    asm volatile(
        "mma.sync.aligned.m16n8k16.row.col.f32.bf16.bf16.f32 "
        "{%0,%1,%2,%3}, {%4,%5,%6,%7}, {%8,%9}, {%0,%1,%2,%3};"
        : "+f"(c[0]), "+f"(c[1]), "+f"(c[2]), "+f"(c[3])
        : "r"(a[0]), "r"(a[1]), "r"(a[2]), "r"(a[3]), "r"(b0), "r"(b1));
}

// ---------------------------------------------------------------------------
// Init: bias-init out + pre-convert x -> bf16 (one-time, L2-hot afterwards)
// ---------------------------------------------------------------------------
__global__ void init_kernel(const float* __restrict__ bias,
                            const float* __restrict__ x,
                            float* __restrict__ out)
{
    const int idx = blockIdx.x * blockDim.x + threadIdx.x;
    if (idx < OUT_F) {
        float b = bfr(bias[idx]);
        #pragma unroll
        for (int s = 0; s < MROWS; s++)
            out[(size_t)s * OUT_F + idx] = b;
    }
    const int stride = gridDim.x * blockDim.x;
    for (int i = idx; i < (MROWS * IN_F) / 2; i += stride) {
        float2 v = ((const float2*)x)[i];
        ((uint32_t*)g_xbf)[i] = pack_bf16x2(v.y, v.x);
    }
}

// ---------------------------------------------------------------------------
// Per CTA: 64 output cols x 1024 K in 32 stages of 32 k-rows.
// BOTH weight tiles and bf16-x tiles stream via cp.async (weights: 3-buffer
// ring, 2 stages in flight; x: per-group double buffer, commit merged with
// the group-start weight stage). B converts on-read ((qw-qz) 5-bit exact in
// bf16); per-group scale in register epilogue on C columns (exact).
// ---------------------------------------------------------------------------
__global__ void __launch_bounds__(THREADS, 5)
qmain(const int* __restrict__ qweight, const int* __restrict__ qzeros,
      const float* __restrict__ scales, float* __restrict__ out)
{
    __shared__ __align__(16) uint8_t xs_raw[2 * XSTILE_B];       // 17408 B
    __shared__ __align__(16) uint8_t ws_raw[WNBUF * WSTAGE_B];   // 26112 B

    uint32_t xs_b, ws_b;
    asm("{ .reg .u64 t; cvta.to.shared.u64 t, %1; cvt.u32.u64 %0, t; }"
        : "=r"(xs_b) : "l"(xs_raw));
    asm("{ .reg .u64 t; cvta.to.shared.u64 t, %1; cvt.u32.u64 %0, t; }"
        : "=r"(ws_b) : "l"(ws_raw));

    const int tid   = threadIdx.x;
    const int w     = tid >> 5;
    const int l     = tid & 31;
    const int bx    = blockIdx.x;
    const int ctile = bx % CTAS_COL;
    const int kq    = bx / CTAS_COL;
    const int o0    = ctile * NTILE;
    const int k0    = kq * KPER;

    const int gid = l >> 2;
    const int tig = l & 3;
    const int nc0 = o0 + w * 16 + gid;      // B column, t=0
    const int nc1 = nc0 + 8;                // B column, t=1
    const int cc  = o0 + w * 16 + 2 * tig;  // C column base

    const uint32_t a_lane_off = (uint32_t)(l & 15) * XROW_B + (uint32_t)(l >> 4) * 16;
    const uint32_t b_off0 = (uint32_t)(2 * tig) * WROW_B + (uint32_t)(w * 16 + gid) * 4;
    const uint32_t b_off1 = b_off0 + 32;    // +8 cols

    // cp.async mapping (weights & x): row = tid>>4 (+8j), seg = tid&15 (16B)
    const int cp_row0 = tid >> 4;
    const int cp_seg  = tid & 15;

    float ct[2][2][4], cg[2][2][4];
    #pragma unroll
    for (int mi = 0; mi < 2; mi++)
        #pragma unroll
        for (int t = 0; t < 2; t++)
            #pragma unroll
            for (int r = 0; r < 4; r++) { ct[mi][t][r] = 0.0f; cg[mi][t][r] = 0.0f; }

    int qz0 = 0, qz1 = 0;

    // weight copy for one 32-row stage (NO commit)
    auto issue_w = [&](int s) {
        const uint32_t dst0 = ws_b + (uint32_t)(s % WNBUF) * WSTAGE_B;
        const int* src0 = qweight + (size_t)(k0 + s * STAGE_K) * OUT_F + o0;
        #pragma unroll
        for (int j = 0; j < 4; j++) {
            int row = cp_row0 + 8 * j;
            uint32_t dst = dst0 + (uint32_t)row * WROW_B + (uint32_t)cp_seg * 16;
            const int* src = src0 + (size_t)row * OUT_F + cp_seg * 4;
            asm volatile("cp.async.cg.shared.global [%0], [%1], 16;" :: "r"(dst), "l"(src));
        }
    };
    // x tile copy for one group (NO commit): 32 s-rows x 256B from g_xbf
    auto issue_x = [&](int g) {
        const uint32_t dst0 = xs_b + (uint32_t)(g & 1) * XSTILE_B;
        const __nv_bfloat16* src0 = g_xbf + (size_t)(k0 + g * GRP);
        #pragma unroll
        for (int j = 0; j < 4; j++) {
            int s = cp_row0 + 8 * j;
            uint32_t dst = dst0 + (uint32_t)s * XROW_B + (uint32_t)cp_seg * 16;
            const __nv_bfloat16* src = src0 + (size_t)s * IN_F + cp_seg * 8;
            asm volatile("cp.async.cg.shared.global [%0], [%1], 16;" :: "r"(dst), "l"(src));
        }
    };

    // ---- prologue: stages 0,1 in flight (stage 0's commit includes x g0) ----
    issue_x(0);
    issue_w(0);
    asm volatile("cp.async.commit_group;" ::: "memory");
    issue_w(1);
    asm volatile("cp.async.commit_group;" ::: "memory");

    for (int st = 0; st < NSTAGES; st++) {
        const int g  = st >> 2;                 // 4 stages per 128k group
        const int gg = (k0 >> 7) + g;

        // wait for stage st's commit (keep st+1 in flight)
        if (st < NSTAGES - 1) asm volatile("cp.async.wait_group 1;" ::: "memory");
        else                  asm volatile("cp.async.wait_group 0;" ::: "memory");
        __syncthreads();   // copies visible to all; prior stage reads done (WAR)

        // issue stage st+2 (+ x tile if it starts a group)
        if (st + 2 < NSTAGES) {
            const int sn = st + 2;
            if ((sn & 3) == 0) issue_x(sn >> 2);
            issue_w(sn);
            asm volatile("cp.async.commit_group;" ::: "memory");
        }

        // group boundary: per-group constants only (x comes via cp.async)
        if ((st & 3) == 0) {
            qz0 = qzeros[(size_t)gg * OUT_F + nc0];
            qz1 = qzeros[(size_t)gg * OUT_F + nc1];
        }

        const uint32_t xbuf = xs_b + (uint32_t)(g & 1) * XSTILE_B;
        const uint32_t rbuf = ws_b + (uint32_t)(st % WNBUF) * WSTAGE_B;

        // ---- 2 k16-steps of this stage ----
        #pragma unroll
        for (int ksl = 0; ksl < 2; ksl++) {
            const int ks = 2 * (st & 3) + ksl;    // kstep within group

            uint32_t a0[4], a1[4];
            uint32_t addr0 = xbuf + a_lane_off + (uint32_t)ks * 32;
            uint32_t addr1 = addr0 + 16u * XROW_B;
            asm volatile("ldmatrix.sync.aligned.m8n8.x4.shared.b16 {%0,%1,%2,%3}, [%4];"
                         : "=r"(a0[0]), "=r"(a0[1]), "=r"(a0[2]), "=r"(a0[3]) : "r"(addr0));
            asm volatile("ldmatrix.sync.aligned.m8n8.x4.shared.b16 {%0,%1,%2,%3}, [%4];"
                         : "=r"(a1[0]), "=r"(a1[1]), "=r"(a1[2]), "=r"(a1[3]) : "r"(addr1));

            const uint32_t rb = rbuf + (uint32_t)(16 * ksl) * WROW_B;

            {   // t = 0: rows 2tig, 2tig+1, 2tig+8, 2tig+9 at local col 16w+gid
                int v0, v1, v2, v3;
                asm volatile("ld.shared.b32 %0, [%1];" : "=r"(v0) : "r"(rb + b_off0));
                asm volatile("ld.shared.b32 %0, [%1];" : "=r"(v1) : "r"(rb + b_off0 + WROW_B));
                asm volatile("ld.shared.b32 %0, [%1];" : "=r"(v2) : "r"(rb + b_off0 + 8 * WROW_B));
                asm volatile("ld.shared.b32 %0, [%1];" : "=r"(v3) : "r"(rb + b_off0 + 9 * WROW_B));
                uint32_t b0 = pack_bf16x2((float)(v1 - qz0), (float)(v0 - qz0));
                uint32_t b1 = pack_bf16x2((float)(v3 - qz0), (float)(v2 - qz0));
                hmma(cg[0][0], a0, b0, b1);
                hmma(cg[1][0], a1, b0, b1);
            }
            {   // t = 1
                int v0, v1, v2, v3;
                asm volatile("ld.shared.b32 %0, [%1];" : "=r"(v0) : "r"(rb + b_off1));
                asm volatile("ld.shared.b32 %0, [%1];" : "=r"(v1) : "r"(rb + b_off1 + WROW_B));
                asm volatile("ld.shared.b32 %0, [%1];" : "=r"(v2) : "r"(rb + b_off1 + 8 * WROW_B));
                asm volatile("ld.shared.b32 %0, [%1];" : "=r"(v3) : "r"(rb + b_off1 + 9 * WROW_B));
                uint32_t b0 = pack_bf16x2((float)(v1 - qz1), (float)(v0 - qz1));
                uint32_t b1 = pack_bf16x2((float)(v3 - qz1), (float)(v2 - qz1));
                hmma(cg[0][1], a0, b0, b1);
                hmma(cg[1][1], a1, b0, b1);
            }
        }

        // ---- group done -> scale epilogue on C columns ----
        if ((st & 3) == 3) {
            const float sA = bfr(scales[(size_t)gg * OUT_F + cc]);
            const float sB = bfr(scales[(size_t)gg * OUT_F + cc + 1]);
            const float sC = bfr(scales[(size_t)gg * OUT_F + cc + 8]);
            const float sD = bfr(scales[(size_t)gg * OUT_F + cc + 9]);
            #pragma unroll
            for (int mi = 0; mi < 2; mi++) {
                ct[mi][0][0] = fmaf(cg[mi][0][0], sA, ct[mi][0][0]);
                ct[mi][0][1] = fmaf(cg[mi][0][1], sB, ct[mi][0][1]);
                ct[mi][0][2] = fmaf(cg[mi][0][2], sA, ct[mi][0][2]);
                ct[mi][0][3] = fmaf(cg[mi][0][3], sB, ct[mi][0][3]);
                ct[mi][1][0] = fmaf(cg[mi][1][0], sC, ct[mi][1][0]);
                ct[mi][1][1] = fmaf(cg[mi][1][1], sD, ct[mi][1][1]);
                ct[mi][1][2] = fmaf(cg[mi][1][2], sC, ct[mi][1][2]);
                ct[mi][1][3] = fmaf(cg[mi][1][3], sD, ct[mi][1][3]);
                #pragma unroll
                for (int t = 0; t < 2; t++)
                    #pragma unroll
                    for (int r = 0; r < 4; r++) cg[mi][t][r] = 0.0f;
            }
        }
    }

    // ---- K-split reduction into bias-initialized output ----
    #pragma unroll
    for (int mi = 0; mi < 2; mi++) {
        int s0 = mi * 16 + gid;
        #pragma unroll
        for (int t = 0; t < 2; t++) {
            int oc = cc + t * 8;
            atomicAdd(&out[(size_t)s0 * OUT_F + oc],           ct[mi][t][0]);
            atomicAdd(&out[(size_t)s0 * OUT_F + oc + 1],       ct[mi][t][1]);
            atomicAdd(&out[(size_t)(s0 + 8) * OUT_F + oc],     ct[mi][t][2]);
            atomicAdd(&out[(size_t)(s0 + 8) * OUT_F + oc + 1], ct[mi][t][3]);
        }
    }
}

// ---------------------------------------------------------------------------
// inputs: x f32[1,32,4096], qweight i32[4096,11008], qzeros i32[32,11008],
//         scales f32[32,11008], bias f32[11008]; output f32[1,32,11008]
// ---------------------------------------------------------------------------
extern "C" void kernel_launch(void* const* d_in, const int* in_sizes, int n_in,
                              void* d_out, int out_size)
{
    const float* x       = (const float*)d_in[0];
    const int*   qweight = (const int*)  d_in[1];
    const int*   qzeros  = (const int*)  d_in[2];
    const float* scales  = (const float*)d_in[3];
    const float* bias    = (const float*)d_in[4];
    float*       out     = (float*)d_out;

    init_kernel<<<86, 256>>>(bias, x, out);
    qmain<<<CTAS_COL * KSPLIT, THREADS>>>(qweight, qzeros, scales, out);
}